// round 17
// baseline (speedup 1.0000x reference)
#include <cuda_runtime.h>
#include <cuda_bf16.h>
#include <math.h>

#define BB   64
#define SS   512
#define HH   768
#define A1N  100
#define NPAD 112
#define NTH  7           // n-tiles per warp (half of 14)
#define C1N  300
#define MM   (BB * SS)
#define KSP  24          // split-K for sentence head (768/24 = 32)
#define KCH  (HH / KSP)  // 32
#define BT   2           // batches per k_sent_a block -> grid 24*32 = 768
#define XS2  20          // Xs stride in u32 — conflict-free A frags
#define WS2  120         // Ws stride in u32 — conflict-free B frags
#define PSPLIT 24        // k_pool list-split factor

// ---------------- scratch (no allocs allowed) ----------------
__device__ unsigned g_w1p[(HH / 2) * NPAD];   // k-paired bf16x2 w1, zero-padded cols
__device__ float g_token_att[MM];
__device__ int   g_list[MM];
__device__ float g_wts[MM];
__device__ int   g_cnt[BB];
__device__ float g_inv_sum[BB];
__device__ float g_pp[BB][PSPLIT][HH];        // partial pooled sums
__device__ float g_spart[BB * KSP * 304];
__device__ float g_maxlab[BB];
__device__ float g_minones[BB];
__device__ float g_maxmask[BB];
__device__ float g_tokloss[BB];
__device__ float g_sent[BB];

__device__ __forceinline__ float sigmoidf_(float x) { return 1.0f / (1.0f + expf(-x)); }

__device__ __forceinline__ float tanh_fast(float x) {
    float r;
    asm("tanh.approx.f32 %0, %1;" : "=f"(r) : "f"(x));
    return r;
}

__device__ __forceinline__ unsigned packbf(float lo, float hi) {
    __nv_bfloat162 v = __floats2bfloat162_rn(lo, hi);
    return *reinterpret_cast<unsigned*>(&v);
}

__device__ __forceinline__ float4 ldg4(const float* p) {
    float4 v;
    asm volatile("ld.global.nc.v4.f32 {%0,%1,%2,%3}, [%4];"
                 : "=f"(v.x), "=f"(v.y), "=f"(v.z), "=f"(v.w) : "l"(p));
    return v;
}

// ---------------- kernel 0: pack w1 to k-paired bf16 ----------------
__global__ __launch_bounds__(256)
void k_prep(const float* __restrict__ w1) {
    const int idx = blockIdx.x * 256 + threadIdx.x;   // over 384*112
    if (idx >= (HH / 2) * NPAD) return;
    const int k2 = idx / NPAD;
    const int c  = idx - k2 * NPAD;
    float lo = 0.0f, hi = 0.0f;
    if (c < A1N) {
        lo = w1[(2 * k2)     * A1N + c];
        hi = w1[(2 * k2 + 1) * A1N + c];
    }
    g_w1p[k2 * NPAD + c] = packbf(lo, hi);
}

// ---------------- kernel 1: token attention (bf16 mma m16n8k16, 256 thr) ----------------
// 8 warps = 4 token-groups(32 tokens) x 2 col-halves(56 cols).  [R8 winner, FROZEN]
__global__ __launch_bounds__(256)
void k_token_att(const float* __restrict__ hidden,
                 const float* __restrict__ b1, const float* __restrict__ w2,
                 const float* __restrict__ b2) {
    __shared__ unsigned Xs[128 * XS2];   // 128 tokens x 16 k2 (bf16x2)
    __shared__ unsigned Ws[16 * WS2];    // 16 k2 x 112 n (bf16x2)
    __shared__ float b1s[NPAD];
    __shared__ float w2s[NPAD];
    __shared__ float psum[128];

    const int tid  = threadIdx.x;
    const int lane = tid & 31;
    const int warp = tid >> 5;
    const int g    = lane >> 2;
    const int tg   = lane & 3;
    const int tokG = warp & 3;
    const int colH = warp >> 2;
    const int rowB = tokG * 32;
    const int ntB  = colH * NTH;
    const int m0b  = blockIdx.x * 128;

    if (tid < NPAD) {
        b1s[tid] = (tid < A1N) ? b1[tid] : 0.0f;
        w2s[tid] = (tid < A1N) ? w2[tid] : 0.0f;
    }
    if (tid < 128) psum[tid] = 0.0f;

    float acc[2][NTH][4];
#pragma unroll
    for (int mt = 0; mt < 2; mt++)
#pragma unroll
        for (int nt = 0; nt < NTH; nt++)
#pragma unroll
            for (int j = 0; j < 4; j++) acc[mt][nt][j] = 0.0f;

    const int xr  = tid >> 3;
    const int xc4 = (tid & 7) << 2;
    const int xu2 = (tid & 7) << 1;

    float4 xv[4];
    unsigned wv[7];

    // prologue: load + pack + stage chunk 0
#pragma unroll
    for (int i = 0; i < 4; i++)
        xv[i] = *reinterpret_cast<const float4*>(
            &hidden[(size_t)(m0b + xr + i * 32) * HH + xc4]);
#pragma unroll
    for (int i = 0; i < 7; i++) {
        const int idx = tid + (i << 8);
        wv[i] = (idx < 1792) ? g_w1p[idx] : 0u;
    }
#pragma unroll
    for (int i = 0; i < 4; i++) {
        Xs[(xr + i * 32) * XS2 + xu2]     = packbf(xv[i].x, xv[i].y);
        Xs[(xr + i * 32) * XS2 + xu2 + 1] = packbf(xv[i].z, xv[i].w);
    }
#pragma unroll
    for (int i = 0; i < 7; i++) {
        const int idx = tid + (i << 8);
        if (idx < 1792) {
            const int kk = idx / NPAD;
            const int c  = idx - kk * NPAD;
            Ws[kk * WS2 + c] = wv[i];
        }
    }
    __syncthreads();

    for (int c = 0; c < HH / 32; c++) {
        if (c + 1 < HH / 32) {
            const int k1 = (c + 1) * 32;
#pragma unroll
            for (int i = 0; i < 4; i++)
                xv[i] = *reinterpret_cast<const float4*>(
                    &hidden[(size_t)(m0b + xr + i * 32) * HH + k1 + xc4]);
            const int wbase = (c + 1) * 16 * NPAD;
#pragma unroll
            for (int i = 0; i < 7; i++) {
                const int idx = tid + (i << 8);
                if (idx < 1792) wv[i] = g_w1p[wbase + idx];
            }
        }

#pragma unroll
        for (int ks = 0; ks < 2; ks++) {
            const int k2o = ks * 8 + tg;
            unsigned a[2][4];
#pragma unroll
            for (int mt = 0; mt < 2; mt++) {
                const int r = rowB + mt * 16 + g;
                a[mt][0] = Xs[r       * XS2 + k2o];
                a[mt][1] = Xs[(r + 8) * XS2 + k2o];
                a[mt][2] = Xs[r       * XS2 + k2o + 4];
                a[mt][3] = Xs[(r + 8) * XS2 + k2o + 4];
            }
#pragma unroll
            for (int nt = 0; nt < NTH; nt++) {
                const int n = (ntB + nt) * 8 + g;
                const unsigned bb0 = Ws[k2o * WS2 + n];
                const unsigned bb1 = Ws[(k2o + 4) * WS2 + n];
#pragma unroll
                for (int mt = 0; mt < 2; mt++) {
                    asm volatile(
                        "mma.sync.aligned.m16n8k16.row.col.f32.bf16.bf16.f32 "
                        "{%0,%1,%2,%3}, {%4,%5,%6,%7}, {%8,%9}, {%0,%1,%2,%3};"
                        : "+f"(acc[mt][nt][0]), "+f"(acc[mt][nt][1]),
                          "+f"(acc[mt][nt][2]), "+f"(acc[mt][nt][3])
                        : "r"(a[mt][0]), "r"(a[mt][1]), "r"(a[mt][2]), "r"(a[mt][3]),
                          "r"(bb0), "r"(bb1));
                }
            }
        }
        __syncthreads();

        if (c + 1 < HH / 32) {
#pragma unroll
            for (int i = 0; i < 4; i++) {
                Xs[(xr + i * 32) * XS2 + xu2]     = packbf(xv[i].x, xv[i].y);
                Xs[(xr + i * 32) * XS2 + xu2 + 1] = packbf(xv[i].z, xv[i].w);
            }
#pragma unroll
            for (int i = 0; i < 7; i++) {
                const int idx = tid + (i << 8);
                if (idx < 1792) {
                    const int kk = idx / NPAD;
                    const int cc = idx - kk * NPAD;
                    Ws[kk * WS2 + cc] = wv[i];
                }
            }
            __syncthreads();
        }
    }

    // epilogue
#pragma unroll
    for (int mt = 0; mt < 2; mt++) {
        float p0 = 0.0f, p1 = 0.0f;
#pragma unroll
        for (int nt = 0; nt < NTH; nt++) {
#pragma unroll
            for (int j = 0; j < 2; j++) {
                const int cc = (ntB + nt) * 8 + tg * 2 + j;
                p0 = fmaf(tanh_fast(acc[mt][nt][j]     + b1s[cc]), w2s[cc], p0);
                p1 = fmaf(tanh_fast(acc[mt][nt][2 + j] + b1s[cc]), w2s[cc], p1);
            }
        }
        p0 += __shfl_xor_sync(0xffffffffu, p0, 1);
        p0 += __shfl_xor_sync(0xffffffffu, p0, 2);
        p1 += __shfl_xor_sync(0xffffffffu, p1, 1);
        p1 += __shfl_xor_sync(0xffffffffu, p1, 2);
        if (tg == 0) {
            atomicAdd(&psum[rowB + mt * 16 + g],     p0);
            atomicAdd(&psum[rowB + mt * 16 + g + 8], p1);
        }
    }
    __syncthreads();
    if (tid < 128)
        g_token_att[m0b + tid] = sigmoidf_(psum[tid] + b2[0]);
}

// ---------------- kernel 2: segment max + masking + stats + compaction ----------------
__global__ __launch_bounds__(SS)
void k_segment(const float* __restrict__ labels, const int* __restrict__ offmap,
               float* __restrict__ out_masked) {
    const int b = blockIdx.x;
    const int s = threadIdx.x;
    const int gi = b * SS + s;

    __shared__ float segmax[SS];
    __shared__ int   wexcl[17];
    __shared__ int   wexcl2[17];
    __shared__ float red[16][5];

    const float att  = g_token_att[gi];
    const int   off0 = offmap[2 * gi];
    const float lab  = labels[gi];
    const bool  ns   = (off0 == 0);

    const int lane = s & 31, warp = s >> 5;
    const unsigned lt = (1u << lane) - 1u;
    const unsigned bal = __ballot_sync(0xffffffffu, ns);
    const int incl = __popc(bal & (0xffffffffu >> (31 - lane)));
    if (lane == 31) wexcl[warp + 1] = incl;
    segmax[s] = 0.0f;
    __syncthreads();

    if (s == 0) {
        int run = 0; wexcl[0] = 0;
        for (int w = 1; w <= 16; w++) { run += wexcl[w]; wexcl[w] = run; }
    }
    __syncthreads();

    const int seg = max(incl + wexcl[warp] - 1, 0);
    atomicMax(reinterpret_cast<int*>(&segmax[seg]), __float_as_int(att));
    __syncthreads();

    const float word_att = ns ? segmax[seg] : 0.0f;
    const bool  msk      = (lab != -1.0f) && ns;
    const float masked   = msk ? word_att : 0.0f;

    if (out_masked) out_masked[gi] = masked;

    const bool nz = (masked != 0.0f);
    const unsigned bal2 = __ballot_sync(0xffffffffu, nz);
    const int pos = __popc(bal2 & lt);
    if (lane == 31) wexcl2[warp + 1] = pos + (nz ? 1 : 0);
    __syncthreads();
    if (s == 0) {
        int run = 0; wexcl2[0] = 0;
        for (int w = 1; w <= 16; w++) { run += wexcl2[w]; wexcl2[w] = run; }
        g_cnt[b] = wexcl2[16];
    }
    __syncthreads();
    if (nz) {
        const int o = wexcl2[warp] + pos;
        g_list[b * SS + o] = s;
        g_wts[b * SS + o]  = masked;
    }

    const float zl = (lab != -1.0f) ? lab : 0.0f;
    const float d  = masked - zl;
    float sumv = masked;
    float sq   = d * d;
    float mx   = masked;
    float ones = nz ? masked : 1.0f;
    float ml   = lab;
#pragma unroll
    for (int off = 16; off > 0; off >>= 1) {
        sumv += __shfl_down_sync(0xffffffffu, sumv, off);
        sq   += __shfl_down_sync(0xffffffffu, sq,   off);
        mx    = fmaxf(mx,   __shfl_down_sync(0xffffffffu, mx,   off));
        ones  = fminf(ones, __shfl_down_sync(0xffffffffu, ones, off));
        ml    = fmaxf(ml,   __shfl_down_sync(0xffffffffu, ml,   off));
    }
    if (lane == 0) {
        red[warp][0] = sumv; red[warp][1] = sq; red[warp][2] = mx;
        red[warp][3] = ones; red[warp][4] = ml;
    }
    __syncthreads();
    if (s == 0) {
        float a = 0.0f, bq = 0.0f, c = -1e30f, dn = 1e30f, e = -1e30f;
        for (int w = 0; w < 16; w++) {
            a += red[w][0]; bq += red[w][1];
            c = fmaxf(c, red[w][2]); dn = fminf(dn, red[w][3]); e = fmaxf(e, red[w][4]);
        }
        g_inv_sum[b] = 1.0f / a;
        g_tokloss[b] = bq;
        g_maxmask[b] = c;
        g_minones[b] = dn;
        g_maxlab[b]  = e;
    }
}

// ---------------- kernel 3: sparse pooling, float4 x list-split x24 ----------------
// grid (BB, PSPLIT), 192 threads; thread t owns h-cols [4t, 4t+4)
__global__ __launch_bounds__(192)
void k_pool(const float* __restrict__ hidden) {
    const int b = blockIdx.x;
    const int p = blockIdx.y;
    const int t = threadIdx.x;
    __shared__ int   ls[SS];
    __shared__ float ws[SS];
    const int   cnt = g_cnt[b];
    const float inv = g_inv_sum[b];
    for (int i = t; i < cnt; i += 192) {
        ls[i] = g_list[b * SS + i];
        ws[i] = g_wts[b * SS + i] * inv;
    }
    __syncthreads();

    const float* hp = hidden + (size_t)b * SS * HH + t * 4;
    float4 a0 = {0,0,0,0}, a1 = {0,0,0,0}, a2 = {0,0,0,0}, a3 = {0,0,0,0};
    int i = p;
    for (; i + 3 * PSPLIT < cnt; i += 4 * PSPLIT) {
        const float4 v0 = ldg4(&hp[(size_t)ls[i]              * HH]);
        const float4 v1 = ldg4(&hp[(size_t)ls[i + PSPLIT]     * HH]);
        const float4 v2 = ldg4(&hp[(size_t)ls[i + 2 * PSPLIT] * HH]);
        const float4 v3 = ldg4(&hp[(size_t)ls[i + 3 * PSPLIT] * HH]);
        const float w0 = ws[i], w1 = ws[i + PSPLIT];
        const float w2 = ws[i + 2 * PSPLIT], w3 = ws[i + 3 * PSPLIT];
        a0.x = fmaf(v0.x, w0, a0.x); a0.y = fmaf(v0.y, w0, a0.y);
        a0.z = fmaf(v0.z, w0, a0.z); a0.w = fmaf(v0.w, w0, a0.w);
        a1.x = fmaf(v1.x, w1, a1.x); a1.y = fmaf(v1.y, w1, a1.y);
        a1.z = fmaf(v1.z, w1, a1.z); a1.w = fmaf(v1.w, w1, a1.w);
        a2.x = fmaf(v2.x, w2, a2.x); a2.y = fmaf(v2.y, w2, a2.y);
        a2.z = fmaf(v2.z, w2, a2.z); a2.w = fmaf(v2.w, w2, a2.w);
        a3.x = fmaf(v3.x, w3, a3.x); a3.y = fmaf(v3.y, w3, a3.y);
        a3.z = fmaf(v3.z, w3, a3.z); a3.w = fmaf(v3.w, w3, a3.w);
    }
    for (; i < cnt; i += PSPLIT) {
        const float4 v = ldg4(&hp[(size_t)ls[i] * HH]);
        const float w = ws[i];
        a0.x = fmaf(v.x, w, a0.x); a0.y = fmaf(v.y, w, a0.y);
        a0.z = fmaf(v.z, w, a0.z); a0.w = fmaf(v.w, w, a0.w);
    }
    float4 r;
    r.x = (a0.x + a1.x) + (a2.x + a3.x);
    r.y = (a0.y + a1.y) + (a2.y + a3.y);
    r.z = (a0.z + a1.z) + (a2.z + a3.z);
    r.w = (a0.w + a1.w) + (a2.w + a3.w);
    *reinterpret_cast<float4*>(&g_pp[b][p][t * 4]) = r;
}

// ---------------- kernel 4: sentence hidden layer (BT=2, grid 768) ----------------
__global__ __launch_bounds__(320)
void k_sent_a(const float* __restrict__ sw1) {
    const int b0 = blockIdx.y * BT;
    const int ks = blockIdx.x;
    const int k0 = ks * KCH;
    const int c  = threadIdx.x;
    __shared__ float ps[BT][KCH];
    if (c < BT * KCH) {
        const int j  = c / KCH;
        const int kk = c - j * KCH;
        const int bj = b0 + j;
        float v = 0.0f;
#pragma unroll
        for (int p = 0; p < PSPLIT; p++) v += g_pp[bj][p][k0 + kk];
        ps[j][kk] = v;
    }
    __syncthreads();

    if (c < C1N) {
        const float* wp = sw1 + (size_t)k0 * C1N + c;
        float acc[BT];
#pragma unroll
        for (int j = 0; j < BT; j++) acc[j] = 0.0f;
#pragma unroll 8
        for (int kk = 0; kk < KCH; kk++) {
            const float w = __ldg(&wp[(size_t)kk * C1N]);
#pragma unroll
            for (int j = 0; j < BT; j++)
                acc[j] = fmaf(ps[j][kk], w, acc[j]);
        }
#pragma unroll
        for (int j = 0; j < BT; j++)
            g_spart[((b0 + j) * KSP + ks) * 304 + c] = acc[j];
    }
}

// ---------------- kernel 5: finish sentence head ----------------
__global__ __launch_bounds__(320)
void k_sent_b(const float* __restrict__ sb1, const float* __restrict__ sw2,
              const float* __restrict__ sb2) {
    const int b = blockIdx.x;
    const int c = threadIdx.x;
    __shared__ float red[10];
    float val = 0.0f;
    if (c < C1N) {
        float s = 0.0f;
#pragma unroll
        for (int j = 0; j < KSP; j++) s += g_spart[(b * KSP + j) * 304 + c];
        val = tanhf(s + sb1[c]) * sw2[c];
    }
    const int lane = c & 31, warp = c >> 5;
#pragma unroll
    for (int off = 16; off > 0; off >>= 1)
        val += __shfl_down_sync(0xffffffffu, val, off);
    if (lane == 0) red[warp] = val;
    __syncthreads();
    if (c == 0) {
        float t = 0.0f;
        for (int w = 0; w < 10; w++) t += red[w];
        g_sent[b] = sigmoidf_(t + sb2[0]);
    }
}

// ---------------- kernel 6: losses + final output ----------------
__global__ __launch_bounds__(64)
void k_final(float* __restrict__ out, int out_size) {
    const int b = threadIdx.x;
    __shared__ float sm[64][4];
    const float sl   = g_sent[b];
    const float slab = g_maxlab[b];
    const float d1 = sl - slab;
    sm[b][0] = d1 * d1;
    sm[b][1] = g_tokloss[b];
    const float mo = g_minones[b];
    sm[b][2] = mo * mo;
    const float d2 = g_maxmask[b] - slab;
    sm[b][3] = d2 * d2;
    const int sent_off = 5 + MM + b;
    if (sent_off < out_size) out[sent_off] = sl;
    __syncthreads();
    if (b == 0) {
        float sloss = 0.0f, tloss = 0.0f, ra = 0.0f, rb = 0.0f;
        for (int i = 0; i < 64; i++) {
            sloss += sm[i][0]; tloss += sm[i][1]; ra += sm[i][2]; rb += sm[i][3];
        }
        const float total = sloss + tloss + 0.01f * (ra + rb);
        if (out_size > 0) out[0] = total;
        if (out_size > 1) out[1] = sloss;
        if (out_size > 2) out[2] = tloss;
        if (out_size > 3) out[3] = ra;
        if (out_size > 4) out[4] = rb;
    }
}

// ---------------- launch ----------------
extern "C" void kernel_launch(void* const* d_in, const int* in_sizes, int n_in,
                              void* d_out, int out_size) {
    const float* hidden = (const float*)d_in[0];
    const float* w1     = (const float*)d_in[1];
    const float* b1     = (const float*)d_in[2];
    const float* w2     = (const float*)d_in[3];
    const float* b2     = (const float*)d_in[4];
    const float* sw1    = (const float*)d_in[5];
    const float* sb1    = (const float*)d_in[6];
    const float* sw2    = (const float*)d_in[7];
    const float* sb2    = (const float*)d_in[8];
    const float* labels = (const float*)d_in[9];
    const int*   offmap = (const int*)d_in[10];
    float* out = (float*)d_out;

    float* out_masked = (out_size >= 5 + MM + BB) ? (out + 5) : nullptr;

    k_prep<<<((HH / 2) * NPAD + 255) / 256, 256>>>(w1);
    k_token_att<<<MM / 128, 256>>>(hidden, b1, w2, b2);
    k_segment<<<BB, SS>>>(labels, offmap, out_masked);
    dim3 g3(BB, PSPLIT);
    k_pool<<<g3, 192>>>(hidden);
    dim3 g4(KSP, BB / BT);
    k_sent_a<<<g4, 320>>>(sw1);
    k_sent_b<<<BB, 320>>>(sb1, sw2, sb2);
    k_final<<<1, 64>>>(out, out_size);
}